// round 3
// baseline (speedup 1.0000x reference)
#include <cuda_runtime.h>
#include <math.h>

#define BATCH 4
#define SEQ   1024
#define NTOK  4096      // BATCH*SEQ
#define DIMV  1024
#define DV    1025
#define HEADS 16
#define DH    64
#define NBH   64        // BATCH*HEADS
#define MLPD  4096

// ---------------- scratch (device globals; allocation-free) ----------------
__device__ float g_q[NTOK * DIMV];
__device__ float g_k[NTOK * DIMV];
__device__ float g_v[NTOK * DIMV];
__device__ float g_qt[NBH * SEQ];
__device__ float g_kt[NBH * SEQ];
__device__ float g_vt[NBH * SEQ];
__device__ float g_sc[(size_t)NBH * SEQ * SEQ];   // 256 MB attention scores
__device__ float g_attn[NTOK * DIMV];
__device__ float g_x2t[NTOK];
__device__ float g_y[NTOK * DIMV];
__device__ float g_x1[NTOK * DV];
__device__ float g_h[(size_t)NTOK * MLPD];        // 64 MB
__device__ float g_ht[NTOK];
__device__ float g_y2[NTOK * DIMV];

// ---------------- reduction helpers ----------------
__device__ __forceinline__ float warpSum(float v) {
    #pragma unroll
    for (int o = 16; o; o >>= 1) v += __shfl_down_sync(0xffffffffu, v, o);
    return v;
}
__device__ __forceinline__ float warpMax(float v) {
    #pragma unroll
    for (int o = 16; o; o >>= 1) v = fmaxf(v, __shfl_down_sync(0xffffffffu, v, o));
    return v;
}
__device__ __forceinline__ float blockSum(float v, float* red) {
    int lane = threadIdx.x & 31, w = threadIdx.x >> 5;
    v = warpSum(v);
    if (lane == 0) red[w] = v;
    __syncthreads();
    if (w == 0) {
        float r = (lane < (int)(blockDim.x >> 5)) ? red[lane] : 0.f;
        r = warpSum(r);
        if (lane == 0) red[0] = r;
    }
    __syncthreads();
    float out = red[0];
    __syncthreads();
    return out;
}
__device__ __forceinline__ float blockMax(float v, float* red) {
    int lane = threadIdx.x & 31, w = threadIdx.x >> 5;
    v = warpMax(v);
    if (lane == 0) red[w] = v;
    __syncthreads();
    if (w == 0) {
        float r = (lane < (int)(blockDim.x >> 5)) ? red[lane] : -1e30f;
        r = warpMax(r);
        if (lane == 0) red[0] = r;
    }
    __syncthreads();
    float out = red[0];
    __syncthreads();
    return out;
}

// ---------------- generic NT SGEMM ----------------
// C[m,n] = sum_k A[m, k] * W[n, koff + k]   (k < Ks)
//        + (At ? At[m] * W[n*ldw + 0] : 0)  + bias[n];  optional ReLU.
// 128x128 tile, BK=8, 256 threads, 8x8 per thread.
__global__ void __launch_bounds__(256) sgemm_nt(
    const float* __restrict__ A, int lda,
    const float* __restrict__ At,
    const float* __restrict__ W, int ldw, int koff,
    const float* __restrict__ bias,
    float* __restrict__ C, int ldc,
    int M, int N, int Ks, int relu)
{
    __shared__ float As[8][128];
    __shared__ float Bs[8][128];
    const int t = threadIdx.x;
    const int bm = blockIdx.y * 128, bn = blockIdx.x * 128;
    const int tx = t & 15, ty = t >> 4;
    const int ar = t >> 1, ac = (t & 1) * 4;

    const float* Ap = A + (size_t)(bm + ar) * lda;
    const float* Wp = W + (size_t)(bn + ar) * ldw + koff;

    float acc[8][8];
    #pragma unroll
    for (int i = 0; i < 8; i++)
        #pragma unroll
        for (int j = 0; j < 8; j++) acc[i][j] = 0.f;

    for (int k0 = 0; k0 < Ks; k0 += 8) {
        #pragma unroll
        for (int j = 0; j < 4; j++) {
            int k = k0 + ac + j;
            As[ac + j][ar] = (k < Ks) ? Ap[k] : 0.f;
            Bs[ac + j][ar] = (k < Ks) ? Wp[k] : 0.f;
        }
        __syncthreads();
        #pragma unroll
        for (int k = 0; k < 8; k++) {
            float a[8], b[8];
            #pragma unroll
            for (int i = 0; i < 4; i++) {
                a[i]     = As[k][ty * 4 + i];
                a[4 + i] = As[k][64 + ty * 4 + i];
            }
            #pragma unroll
            for (int j = 0; j < 4; j++) {
                b[j]     = Bs[k][tx * 4 + j];
                b[4 + j] = Bs[k][64 + tx * 4 + j];
            }
            #pragma unroll
            for (int i = 0; i < 8; i++)
                #pragma unroll
                for (int j = 0; j < 8; j++)
                    acc[i][j] = fmaf(a[i], b[j], acc[i][j]);
        }
        __syncthreads();
    }

    int mrow[8], ncol[8];
    #pragma unroll
    for (int i = 0; i < 8; i++)
        mrow[i] = bm + ((i < 4) ? (ty * 4 + i) : (64 + ty * 4 + i - 4));
    #pragma unroll
    for (int j = 0; j < 8; j++)
        ncol[j] = bn + ((j < 4) ? (tx * 4 + j) : (64 + tx * 4 + j - 4));

    if (At) {
        float at[8], wt[8];
        #pragma unroll
        for (int i = 0; i < 8; i++) at[i] = At[mrow[i]];
        #pragma unroll
        for (int j = 0; j < 8; j++) wt[j] = W[(size_t)ncol[j] * ldw];
        #pragma unroll
        for (int i = 0; i < 8; i++)
            #pragma unroll
            for (int j = 0; j < 8; j++)
                acc[i][j] = fmaf(at[i], wt[j], acc[i][j]);
    }

    float bj[8];
    #pragma unroll
    for (int j = 0; j < 8; j++) bj[j] = bias[ncol[j]];

    #pragma unroll
    for (int i = 0; i < 8; i++)
        #pragma unroll
        for (int j = 0; j < 8; j++) {
            float vv = acc[i][j] + bj[j];
            if (relu) vv = fmaxf(vv, 0.f);
            C[(size_t)mrow[i] * ldc + ncol[j]] = vv;
        }
}

// ---------------- per-head time coords: t = sqrt(sum_d s^2 + 1) ----------------
// one warp per (tensor, b, h, s)
__global__ void __launch_bounds__(256) head_time_kernel(
    const float* __restrict__ q, const float* __restrict__ k,
    const float* __restrict__ v,
    float* __restrict__ qt, float* __restrict__ kt, float* __restrict__ vt)
{
    int w = (blockIdx.x * 256 + threadIdx.x) >> 5;
    int lane = threadIdx.x & 31;
    int tsr = w >> 16;          // 0,1,2
    int rem = w & 65535;        // bh*1024 + s
    int bh = rem >> 10;
    int s = rem & 1023;
    int b = bh >> 4, h = bh & 15;
    const float* src = (tsr == 0) ? q : (tsr == 1) ? k : v;
    float* dst = (tsr == 0) ? qt : (tsr == 1) ? kt : vt;
    const float* p = src + (size_t)(b * SEQ + s) * DIMV + h * DH;
    float v0 = p[lane], v1 = p[lane + 32];
    float sum = v0 * v0 + v1 * v1;
    sum = warpSum(sum);
    if (lane == 0) dst[rem] = sqrtf(sum + 1.0f);
}

// ---------------- attention logits: 0.25*(q.k - qt*kt) ----------------
__global__ void __launch_bounds__(256) scores_kernel(
    const float* __restrict__ qsp, const float* __restrict__ ksp,
    const float* __restrict__ qt, const float* __restrict__ kt,
    float* __restrict__ sc)
{
    const int bh = blockIdx.z, b = bh >> 4, h = bh & 15;
    const int i0 = blockIdx.y * 64, j0 = blockIdx.x * 64;
    const int t = threadIdx.x, tx = t & 15, ty = t >> 4;
    __shared__ float qs[64][65];   // [d][row]
    __shared__ float ks[64][65];
    for (int l = t; l < 4096; l += 256) {
        int r = l >> 6, c = l & 63;
        qs[c][r] = qsp[(size_t)(b * SEQ + i0 + r) * DIMV + h * DH + c];
        ks[c][r] = ksp[(size_t)(b * SEQ + j0 + r) * DIMV + h * DH + c];
    }
    __syncthreads();
    float acc[4][4];
    #pragma unroll
    for (int i = 0; i < 4; i++)
        #pragma unroll
        for (int j = 0; j < 4; j++) acc[i][j] = 0.f;
    #pragma unroll 8
    for (int kk = 0; kk < 64; kk++) {
        float a[4], bv[4];
        #pragma unroll
        for (int i = 0; i < 4; i++) a[i] = qs[kk][ty * 4 + i];
        #pragma unroll
        for (int j = 0; j < 4; j++) bv[j] = ks[kk][tx * 4 + j];
        #pragma unroll
        for (int i = 0; i < 4; i++)
            #pragma unroll
            for (int j = 0; j < 4; j++)
                acc[i][j] = fmaf(a[i], bv[j], acc[i][j]);
    }
    float qti[4], ktj[4];
    #pragma unroll
    for (int i = 0; i < 4; i++) qti[i] = qt[bh * SEQ + i0 + ty * 4 + i];
    #pragma unroll
    for (int j = 0; j < 4; j++) ktj[j] = kt[bh * SEQ + j0 + tx * 4 + j];
    #pragma unroll
    for (int i = 0; i < 4; i++)
        #pragma unroll
        for (int j = 0; j < 4; j++)
            sc[((size_t)bh * SEQ + i0 + ty * 4 + i) * SEQ + j0 + tx * 4 + j] =
                0.25f * (acc[i][j] - qti[i] * ktj[j]);
}

// ---------------- softmax over rows of 1024 (in place) ----------------
__global__ void __launch_bounds__(256) softmax_kernel(float* __restrict__ sc)
{
    float* p = sc + (size_t)blockIdx.x * SEQ;
    int t = threadIdx.x;
    __shared__ float red[32];
    float v0 = p[t], v1 = p[t + 256], v2 = p[t + 512], v3 = p[t + 768];
    float mx = fmaxf(fmaxf(v0, v1), fmaxf(v2, v3));
    mx = blockMax(mx, red);
    v0 = expf(v0 - mx); v1 = expf(v1 - mx); v2 = expf(v2 - mx); v3 = expf(v3 - mx);
    float s = blockSum(v0 + v1 + v2 + v3, red);
    float r = 1.0f / s;
    p[t] = v0 * r; p[t + 256] = v1 * r; p[t + 512] = v2 * r; p[t + 768] = v3 * r;
}

// ---------------- ave = P @ [vt, vsp]; normalize by lorentz norm; write space ----------------
__global__ void __launch_bounds__(256) ave_kernel(
    const float* __restrict__ P, const float* __restrict__ vsp,
    const float* __restrict__ vt, float* __restrict__ osp)
{
    const int bh = blockIdx.y, b = bh >> 4, h = bh & 15;
    const int i0 = blockIdx.x * 64;
    const int t = threadIdx.x, tx = t & 15, ty = t >> 4;
    __shared__ float Ps[64][65];    // [row][j]
    __shared__ float Vs[64][65];    // [j][d], col 64 = vt
    __shared__ float rowp[64][17];
    __shared__ float rowtt[64];
    __shared__ float rown[64];

    float acc[4][4];
    #pragma unroll
    for (int i = 0; i < 4; i++)
        #pragma unroll
        for (int j = 0; j < 4; j++) acc[i][j] = 0.f;
    float accT[4] = {0.f, 0.f, 0.f, 0.f};

    const float* Pbase = P + (size_t)bh * SEQ * SEQ;
    for (int j0 = 0; j0 < SEQ; j0 += 64) {
        for (int l = t; l < 4096; l += 256) {
            int r = l >> 6, c = l & 63;
            Ps[r][c] = Pbase[(size_t)(i0 + r) * SEQ + j0 + c];
            Vs[r][c] = vsp[(size_t)(b * SEQ + j0 + r) * DIMV + h * DH + c];
        }
        if (t < 64) Vs[t][64] = vt[bh * SEQ + j0 + t];
        __syncthreads();
        #pragma unroll 8
        for (int kk = 0; kk < 64; kk++) {
            float a[4], bv[4];
            #pragma unroll
            for (int i = 0; i < 4; i++) a[i] = Ps[ty * 4 + i][kk];
            #pragma unroll
            for (int j = 0; j < 4; j++) bv[j] = Vs[kk][tx * 4 + j];
            #pragma unroll
            for (int i = 0; i < 4; i++)
                #pragma unroll
                for (int j = 0; j < 4; j++)
                    acc[i][j] = fmaf(a[i], bv[j], acc[i][j]);
            if (tx == 0) {
                float vT = Vs[kk][64];
                #pragma unroll
                for (int i = 0; i < 4; i++) accT[i] = fmaf(a[i], vT, accT[i]);
            }
        }
        __syncthreads();
    }

    #pragma unroll
    for (int i = 0; i < 4; i++) {
        float part = 0.f;
        #pragma unroll
        for (int j = 0; j < 4; j++) part += acc[i][j] * acc[i][j];
        rowp[ty * 4 + i][tx] = part;
    }
    if (tx == 0) {
        #pragma unroll
        for (int i = 0; i < 4; i++) rowtt[ty * 4 + i] = accT[i];
    }
    __syncthreads();
    if (t < 64) {
        float s = 0.f;
        #pragma unroll
        for (int xx = 0; xx < 16; xx++) s += rowp[t][xx];
        float tt = rowtt[t];
        float inner = s - tt * tt;
        rown[t] = 1.0f / sqrtf(fmaxf(fabsf(inner), 1e-8f));
    }
    __syncthreads();
    #pragma unroll
    for (int i = 0; i < 4; i++) {
        float rn = rown[ty * 4 + i];
        #pragma unroll
        for (int j = 0; j < 4; j++)
            osp[(size_t)(b * SEQ + i0 + ty * 4 + i) * DIMV + h * DH + tx * 4 + j] =
                acc[i][j] * rn;
    }
}

// ---------------- row time: dst[m] = sqrt(sum_d src[m,d]^2 + 1) ----------------
__global__ void __launch_bounds__(256) row_time_kernel(
    const float* __restrict__ src, float* __restrict__ dst, int W)
{
    int m = blockIdx.x, t = threadIdx.x;
    __shared__ float red[32];
    float s = 0.f;
    for (int d = t; d < W; d += 256) {
        float vv = src[(size_t)m * W + d];
        s += vv * vv;
    }
    s = blockSum(s, red);
    if (t == 0) dst[m] = sqrtf(s + 1.0f);
}

// ---------------- fused: add_time(z) -> midpoint(z,x) -> hyp_layernorm -> add_time ----------------
// ysp: space of z (M x 1024); xfull: M x 1025; out: M x 1025
__global__ void __launch_bounds__(256) mid_ln_kernel(
    const float* __restrict__ ysp, const float* __restrict__ xfull,
    const float* __restrict__ g, const float* __restrict__ bb,
    float* __restrict__ out)
{
    __shared__ float red[32];
    const int m = blockIdx.x, t = threadIdx.x;
    const float* y = ysp + (size_t)m * DIMV;
    const float* x = xfull + (size_t)m * DV;
    float a4[4];
    float sy = 0.f, sa = 0.f, sa2 = 0.f;
    #pragma unroll
    for (int i = 0; i < 4; i++) {
        int d = t + i * 256;
        float yy = y[d];
        float aa = 0.5f * (yy + x[1 + d]);
        a4[i] = aa;
        sy += yy * yy; sa += aa; sa2 += aa * aa;
    }
    float syT = blockSum(sy, red);
    float saT = blockSum(sa, red);
    float sa2T = blockSum(sa2, red);
    float zt = sqrtf(syT + 1.0f);
    float at = 0.5f * (zt + x[0]);
    float inner = sa2T - at * at;
    float rin = 1.0f / sqrtf(fmaxf(fabsf(inner), 1e-8f));
    float mu = saT * rin * (1.0f / 1024.0f);
    float sv = 0.f;
    #pragma unroll
    for (int i = 0; i < 4; i++) {
        float df = a4[i] * rin - mu;
        sv += df * df;
    }
    float var = blockSum(sv, red) * (1.0f / 1024.0f);
    float rstd = rsqrtf(var + 1e-5f);
    float ss = 0.f;
    float* o = out + (size_t)m * DV;
    #pragma unroll
    for (int i = 0; i < 4; i++) {
        int d = t + i * 256;
        float s = (a4[i] * rin - mu) * rstd * g[d] + bb[d];
        o[1 + d] = s;
        ss += s * s;
    }
    float ssT = blockSum(ss, red);
    if (t == 0) o[0] = sqrtf(ssT + 1.0f);
}

// ---------------- launch ----------------
extern "C" void kernel_launch(void* const* d_in, const int* in_sizes, int n_in,
                              void* d_out, int out_size)
{
    const float* x    = (const float*)d_in[0];
    const float* Wq   = (const float*)d_in[1];
    const float* bq   = (const float*)d_in[2];
    const float* Wk   = (const float*)d_in[3];
    const float* bk   = (const float*)d_in[4];
    const float* Wv   = (const float*)d_in[5];
    const float* bv   = (const float*)d_in[6];
    const float* Wo   = (const float*)d_in[7];
    const float* bo   = (const float*)d_in[8];
    const float* ln1g = (const float*)d_in[9];
    const float* ln1b = (const float*)d_in[10];
    const float* W1   = (const float*)d_in[11];
    const float* c1   = (const float*)d_in[12];
    const float* W2   = (const float*)d_in[13];
    const float* c2   = (const float*)d_in[14];
    const float* ln2g = (const float*)d_in[15];
    const float* ln2b = (const float*)d_in[16];
    float* out = (float*)d_out;

    float *q, *k, *v, *qt, *kt, *vt, *sc, *attn, *x2t, *y, *x1, *h, *ht, *y2;
    cudaGetSymbolAddress((void**)&q,   g_q);
    cudaGetSymbolAddress((void**)&k,   g_k);
    cudaGetSymbolAddress((void**)&v,   g_v);
    cudaGetSymbolAddress((void**)&qt,  g_qt);
    cudaGetSymbolAddress((void**)&kt,  g_kt);
    cudaGetSymbolAddress((void**)&vt,  g_vt);
    cudaGetSymbolAddress((void**)&sc,  g_sc);
    cudaGetSymbolAddress((void**)&attn, g_attn);
    cudaGetSymbolAddress((void**)&x2t, g_x2t);
    cudaGetSymbolAddress((void**)&y,   g_y);
    cudaGetSymbolAddress((void**)&x1,  g_x1);
    cudaGetSymbolAddress((void**)&h,   g_h);
    cudaGetSymbolAddress((void**)&ht,  g_ht);
    cudaGetSymbolAddress((void**)&y2,  g_y2);

    dim3 gProj(DIMV / 128, NTOK / 128);   // (8, 32)
    dim3 gMlp(MLPD / 128, NTOK / 128);    // (32, 32)

    // Q/K/V space projections: x(4096x1025) @ W^T
    sgemm_nt<<<gProj, 256>>>(x, DV, nullptr, Wq, DV, 0, bq, q, DIMV, NTOK, DIMV, DV, 0);
    sgemm_nt<<<gProj, 256>>>(x, DV, nullptr, Wk, DV, 0, bk, k, DIMV, NTOK, DIMV, DV, 0);
    sgemm_nt<<<gProj, 256>>>(x, DV, nullptr, Wv, DV, 0, bv, v, DIMV, NTOK, DIMV, DV, 0);

    // per-head time coordinates
    head_time_kernel<<<24576, 256>>>(q, k, v, qt, kt, vt);

    // logits, softmax, weighted ave + lorentz normalization
    scores_kernel<<<dim3(16, 16, NBH), 256>>>(q, k, qt, kt, sc);
    softmax_kernel<<<NBH * SEQ, 256>>>(sc);
    ave_kernel<<<dim3(16, NBH), 256>>>(sc, v, vt, attn);

    // O projection on add_time(attn_space)
    row_time_kernel<<<NTOK, 256>>>(attn, x2t, DIMV);
    sgemm_nt<<<gProj, 256>>>(attn, DIMV, x2t, Wo, DV, 1, bo, y, DIMV, NTOK, DIMV, DIMV, 0);

    // midpoint + LN1 + add_time
    mid_ln_kernel<<<NTOK, 256>>>(y, x, ln1g, ln1b, x1);

    // MLP: hidden (ReLU in epilogue), its row time, then down-proj with time column
    sgemm_nt<<<gMlp, 256>>>(x1, DV, nullptr, W1, DV, 0, c1, h, MLPD, NTOK, MLPD, DV, 1);
    row_time_kernel<<<NTOK, 256>>>(h, ht, MLPD);
    sgemm_nt<<<gProj, 256>>>(h, MLPD, ht, W2, MLPD + 1, 1, c2, y2, DIMV, NTOK, DIMV, MLPD, 0);

    // midpoint + LN2 + add_time -> final output
    mid_ln_kernel<<<NTOK, 256>>>(y2, x1, ln2g, ln2b, out);
}

// round 7
// speedup vs baseline: 2.1521x; 2.1521x over previous
#include <cuda_runtime.h>
#include <math.h>

#define BATCH 4
#define SEQ   1024
#define NTOK  4096
#define DIMV  1024
#define DV    1025
#define HEADS 16
#define DH    64
#define NBH   64
#define MLPD  4096

// ---------------- scratch (device globals; allocation-free) ----------------
__device__ float g_q[NTOK * DIMV];
__device__ float g_k[NTOK * DIMV];
__device__ float g_v[NTOK * DIMV];
__device__ float g_qt[NBH * SEQ];
__device__ float g_kt[NBH * SEQ];
__device__ float g_vt[NBH * SEQ];
__device__ float g_sc[(size_t)NBH * SEQ * SEQ];
__device__ float g_attn[NTOK * DIMV];
__device__ float g_x2t[NTOK];
__device__ float g_y[NTOK * DIMV];
__device__ float g_x1[NTOK * DV];
__device__ float g_h[(size_t)NTOK * MLPD];
__device__ float g_ht[NTOK];
__device__ float g_y2[NTOK * DIMV];

// ---------------- reduction helpers ----------------
__device__ __forceinline__ float warpSum(float v) {
    #pragma unroll
    for (int o = 16; o; o >>= 1) v += __shfl_down_sync(0xffffffffu, v, o);
    return v;
}
__device__ __forceinline__ float warpMax(float v) {
    #pragma unroll
    for (int o = 16; o; o >>= 1) v = fmaxf(v, __shfl_down_sync(0xffffffffu, v, o));
    return v;
}
__device__ __forceinline__ float blockSum(float v, float* red) {
    int lane = threadIdx.x & 31, w = threadIdx.x >> 5;
    v = warpSum(v);
    if (lane == 0) red[w] = v;
    __syncthreads();
    if (w == 0) {
        float r = (lane < (int)(blockDim.x >> 5)) ? red[lane] : 0.f;
        r = warpSum(r);
        if (lane == 0) red[0] = r;
    }
    __syncthreads();
    float out = red[0];
    __syncthreads();
    return out;
}
__device__ __forceinline__ float blockMax(float v, float* red) {
    int lane = threadIdx.x & 31, w = threadIdx.x >> 5;
    v = warpMax(v);
    if (lane == 0) red[w] = v;
    __syncthreads();
    if (w == 0) {
        float r = (lane < (int)(blockDim.x >> 5)) ? red[lane] : -1e30f;
        r = warpMax(r);
        if (lane == 0) red[0] = r;
    }
    __syncthreads();
    float out = red[0];
    __syncthreads();
    return out;
}

// ---------------- tf32 helpers ----------------
__device__ __forceinline__ unsigned f2tf32(float x) {
    unsigned r;
    asm("cvt.rna.tf32.f32 %0, %1;" : "=r"(r) : "f"(x));
    return r;
}
__device__ __forceinline__ void mma_tf32(float c[4],
    unsigned a0, unsigned a1, unsigned a2, unsigned a3,
    unsigned b0, unsigned b1)
{
    asm volatile(
        "mma.sync.aligned.m16n8k8.row.col.f32.tf32.tf32.f32 "
        "{%0,%1,%2,%3}, {%4,%5,%6,%7}, {%8,%9}, {%0,%1,%2,%3};"
        : "+f"(c[0]), "+f"(c[1]), "+f"(c[2]), "+f"(c[3])
        : "r"(a0), "r"(a1), "r"(a2), "r"(a3), "r"(b0), "r"(b1));
}

// ---------------- tf32 tensor-core GEMM ----------------
// C[m,n] = sum_{k<Ks} A[m,k] * W[n, koff+k]
//        + (At ? At[m] * W[n*ldw + 0] : 0)  + bias[n];  optional ReLU.
// Block tile 128(M) x 256(N), BK=16, 256 threads, 8 warps of 64x64,
// tf32 MMA with fp32 accumulate, double-buffered fragment-order smem.
// blockIdx.z selects among up to 3 (W, bias, C) triples (fused QKV).
__global__ void __launch_bounds__(256, 1) mm_tf32(
    const float* __restrict__ A, int lda,
    const float* __restrict__ At,
    const float* __restrict__ Wa, const float* __restrict__ Wb, const float* __restrict__ Wc,
    int ldw, int koff,
    const float* __restrict__ bia, const float* __restrict__ bib, const float* __restrict__ bic,
    float* __restrict__ Ca, float* __restrict__ Cb, float* __restrict__ Cc,
    int ldc, int Ks, int relu)
{
    const int z = blockIdx.z;
    const float* W    = (z == 0) ? Wa  : (z == 1) ? Wb  : Wc;
    const float* bias = (z == 0) ? bia : (z == 1) ? bib : bic;
    float*       C    = (z == 0) ? Ca  : (z == 1) ? Cb  : Cc;

    __shared__ unsigned As[2][2][2][4][4][32];
    __shared__ unsigned Bs[2][2][32][32][2];

    const int t = threadIdx.x;
    const int lane = t & 31, warp = t >> 5;
    const int wm = warp >> 2;
    const int wn = warp & 3;
    const int bm = blockIdx.y * 128;
    const int bn = blockIdx.x * 256;

    const int ar = t >> 2;
    const int ac = (t & 3) * 4;

    float pfA[8];
    float pfB[16];

    float acc[4][8][4];
    #pragma unroll
    for (int mf = 0; mf < 4; mf++)
        #pragma unroll
        for (int nf = 0; nf < 8; nf++)
            #pragma unroll
            for (int s = 0; s < 4; s++) acc[mf][nf][s] = 0.f;

    const int ntile = (Ks + 15) >> 4;

#define GLOAD(K0)                                                            \
    {                                                                        \
        _Pragma("unroll")                                                    \
        for (int j = 0; j < 4; j++) {                                        \
            int kg = (K0) + ac + j;                                          \
            bool p = kg < Ks;                                                \
            pfA[j]     = p ? A[(size_t)(bm + ar) * lda + kg] : 0.f;          \
            pfA[4 + j] = p ? A[(size_t)(bm + ar + 64) * lda + kg] : 0.f;     \
        }                                                                    \
        _Pragma("unroll")                                                    \
        for (int pp = 0; pp < 4; pp++) {                                     \
            int n = bn + ar + pp * 64;                                       \
            _Pragma("unroll")                                                \
            for (int j = 0; j < 4; j++) {                                    \
                int kg = (K0) + ac + j;                                      \
                pfB[pp * 4 + j] = (kg < Ks)                                  \
                    ? W[(size_t)n * ldw + koff + kg] : 0.f;                  \
            }                                                                \
        }                                                                    \
    }

#define SSTORE(BUF)                                                          \
    {                                                                        \
        _Pragma("unroll")                                                    \
        for (int half = 0; half < 2; half++) {                               \
            int ml = ar + half * 64;                                         \
            int rr = ml & 15, mf = (ml >> 4) & 3, wmi = ml >> 6;             \
            _Pragma("unroll")                                                \
            for (int j = 0; j < 4; j++) {                                    \
                int kk = ac + j;                                             \
                int k8 = kk >> 3, cp = kk & 7;                               \
                int slot = ((rr >> 3) & 1) | ((cp >= 4) ? 2 : 0);            \
                int li = (rr & 7) * 4 + (cp & 3);                            \
                As[BUF][k8][wmi][mf][slot][li] = f2tf32(pfA[half * 4 + j]);  \
            }                                                                \
        }                                                                    \
        _Pragma("unroll")                                                    \
        for (int pp = 0; pp < 4; pp++) {                                     \
            int nl = ar + pp * 64;                                           \
            int ng = nl >> 3, n8 = nl & 7;                                   \
            _Pragma("unroll")                                                \
            for (int j = 0; j < 4; j++) {                                    \
                int kk = ac + j;                                             \
                int k8 = kk >> 3, cp = kk & 7;                               \
                int slot = (cp >= 4) ? 1 : 0;                                \
                int li = n8 * 4 + (cp & 3);                                  \
                Bs[BUF][k8][ng][li][slot] = f2tf32(pfB[pp * 4 + j]);         \
            }                                                                \
        }                                                                    \
    }

    GLOAD(0);
    SSTORE(0);
    __syncthreads();

    int buf = 0;
    for (int tile = 0; tile < ntile; tile++) {
        if (tile + 1 < ntile) GLOAD((tile + 1) << 4);

        #pragma unroll
        for (int k8 = 0; k8 < 2; k8++) {
            unsigned af[4][4];
            #pragma unroll
            for (int mf = 0; mf < 4; mf++)
                #pragma unroll
                for (int s = 0; s < 4; s++)
                    af[mf][s] = As[buf][k8][wm][mf][s][lane];
            unsigned bfr[8][2];
            #pragma unroll
            for (int nf = 0; nf < 8; nf++) {
                uint2 bv = *(const uint2*)&Bs[buf][k8][wn * 8 + nf][lane][0];
                bfr[nf][0] = bv.x; bfr[nf][1] = bv.y;
            }
            #pragma unroll
            for (int mf = 0; mf < 4; mf++)
                #pragma unroll
                for (int nf = 0; nf < 8; nf++)
                    mma_tf32(acc[mf][nf],
                             af[mf][0], af[mf][1], af[mf][2], af[mf][3],
                             bfr[nf][0], bfr[nf][1]);
        }

        if (tile + 1 < ntile) SSTORE(buf ^ 1);
        __syncthreads();
        buf ^= 1;
    }

    #pragma unroll
    for (int mf = 0; mf < 4; mf++) {
        int m0 = bm + wm * 64 + mf * 16 + (lane >> 2);
        float at0 = 0.f, at1 = 0.f;
        if (At) { at0 = At[m0]; at1 = At[m0 + 8]; }
        #pragma unroll
        for (int nf = 0; nf < 8; nf++) {
            int n0 = bn + wn * 64 + nf * 8 + (lane & 3) * 2;
            float wt0 = 0.f, wt1 = 0.f;
            if (At) { wt0 = W[(size_t)n0 * ldw]; wt1 = W[(size_t)(n0 + 1) * ldw]; }
            float b0v = bias[n0], b1v = bias[n0 + 1];
            float v00 = acc[mf][nf][0] + at0 * wt0 + b0v;
            float v01 = acc[mf][nf][1] + at0 * wt1 + b1v;
            float v10 = acc[mf][nf][2] + at1 * wt0 + b0v;
            float v11 = acc[mf][nf][3] + at1 * wt1 + b1v;
            if (relu) {
                v00 = fmaxf(v00, 0.f); v01 = fmaxf(v01, 0.f);
                v10 = fmaxf(v10, 0.f); v11 = fmaxf(v11, 0.f);
            }
            *(float2*)&C[(size_t)m0 * ldc + n0]       = make_float2(v00, v01);
            *(float2*)&C[(size_t)(m0 + 8) * ldc + n0] = make_float2(v10, v11);
        }
    }
#undef GLOAD
#undef SSTORE
}

// ---------------- per-head time coords ----------------
__global__ void __launch_bounds__(256) head_time_kernel(
    const float* __restrict__ q, const float* __restrict__ k,
    const float* __restrict__ v,
    float* __restrict__ qt, float* __restrict__ kt, float* __restrict__ vt)
{
    int w = (blockIdx.x * 256 + threadIdx.x) >> 5;
    int lane = threadIdx.x & 31;
    int tsr = w >> 16;
    int rem = w & 65535;
    int bh = rem >> 10;
    int s = rem & 1023;
    int b = bh >> 4, h = bh & 15;
    const float* src = (tsr == 0) ? q : (tsr == 1) ? k : v;
    float* dst = (tsr == 0) ? qt : (tsr == 1) ? kt : vt;
    const float* p = src + (size_t)(b * SEQ + s) * DIMV + h * DH;
    float v0 = p[lane], v1 = p[lane + 32];
    float sum = v0 * v0 + v1 * v1;
    sum = warpSum(sum);
    if (lane == 0) dst[rem] = sqrtf(sum + 1.0f);
}

// ---------------- attention logits ----------------
__global__ void __launch_bounds__(256) scores_kernel(
    const float* __restrict__ qsp, const float* __restrict__ ksp,
    const float* __restrict__ qt, const float* __restrict__ kt,
    float* __restrict__ sc)
{
    const int bh = blockIdx.z, b = bh >> 4, h = bh & 15;
    const int i0 = blockIdx.y * 64, j0 = blockIdx.x * 64;
    const int t = threadIdx.x, tx = t & 15, ty = t >> 4;
    __shared__ float qs[64][65];
    __shared__ float ks[64][65];
    for (int l = t; l < 4096; l += 256) {
        int r = l >> 6, c = l & 63;
        qs[c][r] = qsp[(size_t)(b * SEQ + i0 + r) * DIMV + h * DH + c];
        ks[c][r] = ksp[(size_t)(b * SEQ + j0 + r) * DIMV + h * DH + c];
    }
    __syncthreads();
    float acc[4][4];
    #pragma unroll
    for (int i = 0; i < 4; i++)
        #pragma unroll
        for (int j = 0; j < 4; j++) acc[i][j] = 0.f;
    #pragma unroll 8
    for (int kk = 0; kk < 64; kk++) {
        float a[4], bv[4];
        #pragma unroll
        for (int i = 0; i < 4; i++) a[i] = qs[kk][ty * 4 + i];
        #pragma unroll
        for (int j = 0; j < 4; j++) bv[j] = ks[kk][tx * 4 + j];
        #pragma unroll
        for (int i = 0; i < 4; i++)
            #pragma unroll
            for (int j = 0; j < 4; j++)
                acc[i][j] = fmaf(a[i], bv[j], acc[i][j]);
    }
    float qti[4], ktj[4];
    #pragma unroll
    for (int i = 0; i < 4; i++) qti[i] = qt[bh * SEQ + i0 + ty * 4 + i];
    #pragma unroll
    for (int j = 0; j < 4; j++) ktj[j] = kt[bh * SEQ + j0 + tx * 4 + j];
    #pragma unroll
    for (int i = 0; i < 4; i++)
        #pragma unroll
        for (int j = 0; j < 4; j++)
            sc[((size_t)bh * SEQ + i0 + ty * 4 + i) * SEQ + j0 + tx * 4 + j] =
                0.25f * (acc[i][j] - qti[i] * ktj[j]);
}

// ---------------- softmax (in place) ----------------
__global__ void __launch_bounds__(256) softmax_kernel(float* __restrict__ sc)
{
    float* p = sc + (size_t)blockIdx.x * SEQ;
    int t = threadIdx.x;
    __shared__ float red[32];
    float v0 = p[t], v1 = p[t + 256], v2 = p[t + 512], v3 = p[t + 768];
    float mx = fmaxf(fmaxf(v0, v1), fmaxf(v2, v3));
    mx = blockMax(mx, red);
    v0 = expf(v0 - mx); v1 = expf(v1 - mx); v2 = expf(v2 - mx); v3 = expf(v3 - mx);
    float s = blockSum(v0 + v1 + v2 + v3, red);
    float r = 1.0f / s;
    p[t] = v0 * r; p[t + 256] = v1 * r; p[t + 512] = v2 * r; p[t + 768] = v3 * r;
}

// ---------------- ave = P @ [vt, vsp]; normalize; write space ----------------
__global__ void __launch_bounds__(256) ave_kernel(
    const float* __restrict__ P, const float* __restrict__ vsp,
    const float* __restrict__ vt, float* __restrict__ osp)
{
    const int bh = blockIdx.y, b = bh >> 4, h = bh & 15;
    const int i0 = blockIdx.x * 64;
    const int t = threadIdx.x, tx = t & 15, ty = t >> 4;
    __shared__ float Ps[64][65];
    __shared__ float Vs[64][65];
    __shared__ float rowp[64][17];
    __shared__ float rowtt[64];
    __shared__ float rown[64];

    float acc[4][4];
    #pragma unroll
    for (int i = 0; i < 4; i++)
        #pragma unroll
        for (int j = 0; j < 4; j++) acc[i][j] = 0.f;
    float accT[4] = {0.f, 0.f, 0.f, 0.f};

    const float* Pbase = P + (size_t)bh * SEQ * SEQ;
    for (int j0 = 0; j0 < SEQ; j0 += 64) {
        for (int l = t; l < 4096; l += 256) {
            int r = l >> 6, c = l & 63;
            Ps[r][c] = Pbase[(size_t)(i0 + r) * SEQ + j0 + c];
            Vs[r][c] = vsp[(size_t)(b * SEQ + j0 + r) * DIMV + h * DH + c];
        }
        if (t < 64) Vs[t][64] = vt[bh * SEQ + j0 + t];
        __syncthreads();
        #pragma unroll 8
        for (int kk = 0; kk < 64; kk++) {
            float a[4], bv[4];
            #pragma unroll
            for (int i = 0; i < 4; i++) a[i] = Ps[ty * 4 + i][kk];
            #pragma unroll
            for (int j = 0; j < 4; j++) bv[j] = Vs[kk][tx * 4 + j];
            #pragma unroll
            for (int i = 0; i < 4; i++)
                #pragma unroll
                for (int j = 0; j < 4; j++)
                    acc[i][j] = fmaf(a[i], bv[j], acc[i][j]);
            if (tx == 0) {
                float vT = Vs[kk][64];
                #pragma unroll
                for (int i = 0; i < 4; i++) accT[i] = fmaf(a[i], vT, accT[i]);
            }
        }
        __syncthreads();
    }

    #pragma unroll
    for (int i = 0; i < 4; i++) {
        float part = 0.f;
        #pragma unroll
        for (int j = 0; j < 4; j++) part += acc[i][j] * acc[i][j];
        rowp[ty * 4 + i][tx] = part;
    }
    if (tx == 0) {
        #pragma unroll
        for (int i = 0; i < 4; i++) rowtt[ty * 4 + i] = accT[i];
    }
    __syncthreads();
    if (t < 64) {
        float s = 0.f;
        #pragma unroll
        for (int xx = 0; xx < 16; xx++) s += rowp[t][xx];
        float tt = rowtt[t];
        float inner = s - tt * tt;
        rown[t] = 1.0f / sqrtf(fmaxf(fabsf(inner), 1e-8f));
    }
    __syncthreads();
    #pragma unroll
    for (int i = 0; i < 4; i++) {
        float rn = rown[ty * 4 + i];
        #pragma unroll
        for (int j = 0; j < 4; j++)
            osp[(size_t)(b * SEQ + i0 + ty * 4 + i) * DIMV + h * DH + tx * 4 + j] =
                acc[i][j] * rn;
    }
}

// ---------------- row time ----------------
__global__ void __launch_bounds__(256) row_time_kernel(
    const float* __restrict__ src, float* __restrict__ dst, int W)
{
    int m = blockIdx.x, t = threadIdx.x;
    __shared__ float red[32];
    float s = 0.f;
    for (int d = t; d < W; d += 256) {
        float vv = src[(size_t)m * W + d];
        s += vv * vv;
    }
    s = blockSum(s, red);
    if (t == 0) dst[m] = sqrtf(s + 1.0f);
}

// ---------------- fused: add_time -> midpoint -> hyp_layernorm -> add_time ----------------
__global__ void __launch_bounds__(256) mid_ln_kernel(
    const float* __restrict__ ysp, const float* __restrict__ xfull,
    const float* __restrict__ g, const float* __restrict__ bb,
    float* __restrict__ out)
{
    __shared__ float red[32];
    const int m = blockIdx.x, t = threadIdx.x;
    const float* y = ysp + (size_t)m * DIMV;
    const float* x = xfull + (size_t)m * DV;
    float a4[4];
    float sy = 0.f, sa = 0.f, sa2 = 0.f;
    #pragma unroll
    for (int i = 0; i < 4; i++) {
        int d = t + i * 256;
        float yy = y[d];
        float aa = 0.5f * (yy + x[1 + d]);
        a4[i] = aa;
        sy += yy * yy; sa += aa; sa2 += aa * aa;
    }
    float syT = blockSum(sy, red);
    float saT = blockSum(sa, red);
    float sa2T = blockSum(sa2, red);
    float zt = sqrtf(syT + 1.0f);
    float at = 0.5f * (zt + x[0]);
    float inner = sa2T - at * at;
    float rin = 1.0f / sqrtf(fmaxf(fabsf(inner), 1e-8f));
    float mu = saT * rin * (1.0f / 1024.0f);
    float sv = 0.f;
    #pragma unroll
    for (int i = 0; i < 4; i++) {
        float df = a4[i] * rin - mu;
        sv += df * df;
    }
    float var = blockSum(sv, red) * (1.0f / 1024.0f);
    float rstd = rsqrtf(var + 1e-5f);
    float ss = 0.f;
    float* o = out + (size_t)m * DV;
    #pragma unroll
    for (int i = 0; i < 4; i++) {
        int d = t + i * 256;
        float s = (a4[i] * rin - mu) * rstd * g[d] + bb[d];
        o[1 + d] = s;
        ss += s * s;
    }
    float ssT = blockSum(ss, red);
    if (t == 0) o[0] = sqrtf(ssT + 1.0f);
}

// ---------------- launch ----------------
extern "C" void kernel_launch(void* const* d_in, const int* in_sizes, int n_in,
                              void* d_out, int out_size)
{
    const float* x    = (const float*)d_in[0];
    const float* Wq   = (const float*)d_in[1];
    const float* bq   = (const float*)d_in[2];
    const float* Wk   = (const float*)d_in[3];
    const float* bk   = (const float*)d_in[4];
    const float* Wv   = (const float*)d_in[5];
    const float* bv   = (const float*)d_in[6];
    const float* Wo   = (const float*)d_in[7];
    const float* bo   = (const float*)d_in[8];
    const float* ln1g = (const float*)d_in[9];
    const float* ln1b = (const float*)d_in[10];
    const float* W1   = (const float*)d_in[11];
    const float* c1   = (const float*)d_in[12];
    const float* W2   = (const float*)d_in[13];
    const float* c2   = (const float*)d_in[14];
    const float* ln2g = (const float*)d_in[15];
    const float* ln2b = (const float*)d_in[16];
    float* out = (float*)d_out;

    float *q, *k, *v, *qt, *kt, *vt, *sc, *attn, *x2t, *y, *x1, *h, *ht, *y2;
    cudaGetSymbolAddress((void**)&q,   g_q);
    cudaGetSymbolAddress((void**)&k,   g_k);
    cudaGetSymbolAddress((void**)&v,   g_v);
    cudaGetSymbolAddress((void**)&qt,  g_qt);
    cudaGetSymbolAddress((void**)&kt,  g_kt);
    cudaGetSymbolAddress((void**)&vt,  g_vt);
    cudaGetSymbolAddress((void**)&sc,  g_sc);
    cudaGetSymbolAddress((void**)&attn, g_attn);
    cudaGetSymbolAddress((void**)&x2t, g_x2t);
    cudaGetSymbolAddress((void**)&y,   g_y);
    cudaGetSymbolAddress((void**)&x1,  g_x1);
    cudaGetSymbolAddress((void**)&h,   g_h);
    cudaGetSymbolAddress((void**)&ht,  g_ht);
    cudaGetSymbolAddress((void**)&y2,  g_y2);

    // fused QKV projections (tf32 tensor cores)
    mm_tf32<<<dim3(DIMV / 256, NTOK / 128, 3), 256>>>(
        x, DV, nullptr,
        Wq, Wk, Wv, DV, 0,
        bq, bk, bv,
        q, k, v, DIMV, DV, 0);

    head_time_kernel<<<24576, 256>>>(q, k, v, qt, kt, vt);

    scores_kernel<<<dim3(16, 16, NBH), 256>>>(q, k, qt, kt, sc);
    softmax_kernel<<<NBH * SEQ, 256>>>(sc);
    ave_kernel<<<dim3(16, NBH), 256>>>(sc, v, vt, attn);

    row_time_kernel<<<NTOK, 256>>>(attn, x2t, DIMV);
    mm_tf32<<<dim3(DIMV / 256, NTOK / 128, 1), 256>>>(
        attn, DIMV, x2t,
        Wo, Wo, Wo, DV, 1,
        bo, bo, bo,
        y, y, y, DIMV, DIMV, 0);

    mid_ln_kernel<<<NTOK, 256>>>(y, x, ln1g, ln1b, x1);

    mm_tf32<<<dim3(MLPD / 256, NTOK / 128, 1), 256>>>(
        x1, DV, nullptr,
        W1, W1, W1, DV, 0,
        c1, c1, c1,
        h, h, h, MLPD, DV, 1);
    row_time_kernel<<<NTOK, 256>>>(h, ht, MLPD);
    mm_tf32<<<dim3(DIMV / 256, NTOK / 128, 1), 256>>>(
        h, MLPD, ht,
        W2, W2, W2, MLPD + 1, 1,
        c2, c2, c2,
        y2, y2, y2, DIMV, MLPD, 0);

    mid_ln_kernel<<<NTOK, 256>>>(y2, x1, ln2g, ln2b, out);
}

// round 9
// speedup vs baseline: 2.5414x; 1.1809x over previous
#include <cuda_runtime.h>
#include <math.h>

#define BATCH 4
#define SEQ   1024
#define NTOK  4096
#define DIMV  1024
#define DV    1025
#define HEADS 16
#define DH    64
#define NBH   64
#define MLPD  4096

// ---------------- scratch (device globals; allocation-free) ----------------
__device__ float g_q[NTOK * DIMV];
__device__ float g_k[NTOK * DIMV];
__device__ float g_v[NTOK * DIMV];
__device__ float g_qt[NBH * SEQ];
__device__ float g_kt[NBH * SEQ];
__device__ float g_vt[NBH * SEQ];
__device__ float g_attn[NTOK * DIMV];
__device__ float g_x2t[NTOK];
__device__ float g_y[NTOK * DIMV];
__device__ float g_x1[NTOK * DV];
__device__ float g_h[(size_t)NTOK * MLPD];
__device__ float g_ht[NTOK];
__device__ float g_y2[NTOK * DIMV];

// ---------------- reduction helpers ----------------
__device__ __forceinline__ float warpSum(float v) {
    #pragma unroll
    for (int o = 16; o; o >>= 1) v += __shfl_down_sync(0xffffffffu, v, o);
    return v;
}
__device__ __forceinline__ float blockSum(float v, float* red) {
    int lane = threadIdx.x & 31, w = threadIdx.x >> 5;
    v = warpSum(v);
    if (lane == 0) red[w] = v;
    __syncthreads();
    if (w == 0) {
        float r = (lane < (int)(blockDim.x >> 5)) ? red[lane] : 0.f;
        r = warpSum(r);
        if (lane == 0) red[0] = r;
    }
    __syncthreads();
    float out = red[0];
    __syncthreads();
    return out;
}

// ---------------- tf32 helpers ----------------
__device__ __forceinline__ unsigned f2tf32(float x) {
    unsigned r;
    asm("cvt.rna.tf32.f32 %0, %1;" : "=r"(r) : "f"(x));
    return r;
}
__device__ __forceinline__ void mma_tf32(float c[4],
    unsigned a0, unsigned a1, unsigned a2, unsigned a3,
    unsigned b0, unsigned b1)
{
    asm volatile(
        "mma.sync.aligned.m16n8k8.row.col.f32.tf32.tf32.f32 "
        "{%0,%1,%2,%3}, {%4,%5,%6,%7}, {%8,%9}, {%0,%1,%2,%3};"
        : "+f"(c[0]), "+f"(c[1]), "+f"(c[2]), "+f"(c[3])
        : "r"(a0), "r"(a1), "r"(a2), "r"(a3), "r"(b0), "r"(b1));
}

// ---------------- tf32 tensor-core GEMM (validated R7) ----------------
__global__ void __launch_bounds__(256, 1) mm_tf32(
    const float* __restrict__ A, int lda,
    const float* __restrict__ At,
    const float* __restrict__ Wa, const float* __restrict__ Wb, const float* __restrict__ Wc,
    int ldw, int koff,
    const float* __restrict__ bia, const float* __restrict__ bib, const float* __restrict__ bic,
    float* __restrict__ Ca, float* __restrict__ Cb, float* __restrict__ Cc,
    int ldc, int Ks, int relu)
{
    const int z = blockIdx.z;
    const float* W    = (z == 0) ? Wa  : (z == 1) ? Wb  : Wc;
    const float* bias = (z == 0) ? bia : (z == 1) ? bib : bic;
    float*       C    = (z == 0) ? Ca  : (z == 1) ? Cb  : Cc;

    __shared__ unsigned As[2][2][2][4][4][32];
    __shared__ unsigned Bs[2][2][32][32][2];

    const int t = threadIdx.x;
    const int lane = t & 31, warp = t >> 5;
    const int wm = warp >> 2;
    const int wn = warp & 3;
    const int bm = blockIdx.y * 128;
    const int bn = blockIdx.x * 256;

    const int ar = t >> 2;
    const int ac = (t & 3) * 4;

    float pfA[8];
    float pfB[16];

    float acc[4][8][4];
    #pragma unroll
    for (int mf = 0; mf < 4; mf++)
        #pragma unroll
        for (int nf = 0; nf < 8; nf++)
            #pragma unroll
            for (int s = 0; s < 4; s++) acc[mf][nf][s] = 0.f;

    const int ntile = (Ks + 15) >> 4;

#define GLOAD(K0)                                                            \
    {                                                                        \
        _Pragma("unroll")                                                    \
        for (int j = 0; j < 4; j++) {                                        \
            int kg = (K0) + ac + j;                                          \
            bool p = kg < Ks;                                                \
            pfA[j]     = p ? A[(size_t)(bm + ar) * lda + kg] : 0.f;          \
            pfA[4 + j] = p ? A[(size_t)(bm + ar + 64) * lda + kg] : 0.f;     \
        }                                                                    \
        _Pragma("unroll")                                                    \
        for (int pp = 0; pp < 4; pp++) {                                     \
            int n = bn + ar + pp * 64;                                       \
            _Pragma("unroll")                                                \
            for (int j = 0; j < 4; j++) {                                    \
                int kg = (K0) + ac + j;                                      \
                pfB[pp * 4 + j] = (kg < Ks)                                  \
                    ? W[(size_t)n * ldw + koff + kg] : 0.f;                  \
            }                                                                \
        }                                                                    \
    }

#define SSTORE(BUF)                                                          \
    {                                                                        \
        _Pragma("unroll")                                                    \
        for (int half = 0; half < 2; half++) {                               \
            int ml = ar + half * 64;                                         \
            int rr = ml & 15, mf = (ml >> 4) & 3, wmi = ml >> 6;             \
            _Pragma("unroll")                                                \
            for (int j = 0; j < 4; j++) {                                    \
                int kk = ac + j;                                             \
                int k8 = kk >> 3, cp = kk & 7;                               \
                int slot = ((rr >> 3) & 1) | ((cp >= 4) ? 2 : 0);            \
                int li = (rr & 7) * 4 + (cp & 3);                            \
                As[BUF][k8][wmi][mf][slot][li] = f2tf32(pfA[half * 4 + j]);  \
            }                                                                \
        }                                                                    \
        _Pragma("unroll")                                                    \
        for (int pp = 0; pp < 4; pp++) {                                     \
            int nl = ar + pp * 64;                                           \
            int ng = nl >> 3, n8 = nl & 7;                                   \
            _Pragma("unroll")                                                \
            for (int j = 0; j < 4; j++) {                                    \
                int kk = ac + j;                                             \
                int k8 = kk >> 3, cp = kk & 7;                               \
                int slot = (cp >= 4) ? 1 : 0;                                \
                int li = n8 * 4 + (cp & 3);                                  \
                Bs[BUF][k8][ng][li][slot] = f2tf32(pfB[pp * 4 + j]);         \
            }                                                                \
        }                                                                    \
    }

    GLOAD(0);
    SSTORE(0);
    __syncthreads();

    int buf = 0;
    for (int tile = 0; tile < ntile; tile++) {
        if (tile + 1 < ntile) GLOAD((tile + 1) << 4);

        #pragma unroll
        for (int k8 = 0; k8 < 2; k8++) {
            unsigned af[4][4];
            #pragma unroll
            for (int mf = 0; mf < 4; mf++)
                #pragma unroll
                for (int s = 0; s < 4; s++)
                    af[mf][s] = As[buf][k8][wm][mf][s][lane];
            unsigned bfr[8][2];
            #pragma unroll
            for (int nf = 0; nf < 8; nf++) {
                uint2 bv = *(const uint2*)&Bs[buf][k8][wn * 8 + nf][lane][0];
                bfr[nf][0] = bv.x; bfr[nf][1] = bv.y;
            }
            #pragma unroll
            for (int mf = 0; mf < 4; mf++)
                #pragma unroll
                for (int nf = 0; nf < 8; nf++)
                    mma_tf32(acc[mf][nf],
                             af[mf][0], af[mf][1], af[mf][2], af[mf][3],
                             bfr[nf][0], bfr[nf][1]);
        }

        if (tile + 1 < ntile) SSTORE(buf ^ 1);
        __syncthreads();
        buf ^= 1;
    }

    #pragma unroll
    for (int mf = 0; mf < 4; mf++) {
        int m0 = bm + wm * 64 + mf * 16 + (lane >> 2);
        float at0 = 0.f, at1 = 0.f;
        if (At) { at0 = At[m0]; at1 = At[m0 + 8]; }
        #pragma unroll
        for (int nf = 0; nf < 8; nf++) {
            int n0 = bn + wn * 64 + nf * 8 + (lane & 3) * 2;
            float wt0 = 0.f, wt1 = 0.f;
            if (At) { wt0 = W[(size_t)n0 * ldw]; wt1 = W[(size_t)(n0 + 1) * ldw]; }
            float b0v = bias[n0], b1v = bias[n0 + 1];
            float v00 = acc[mf][nf][0] + at0 * wt0 + b0v;
            float v01 = acc[mf][nf][1] + at0 * wt1 + b1v;
            float v10 = acc[mf][nf][2] + at1 * wt0 + b0v;
            float v11 = acc[mf][nf][3] + at1 * wt1 + b1v;
            if (relu) {
                v00 = fmaxf(v00, 0.f); v01 = fmaxf(v01, 0.f);
                v10 = fmaxf(v10, 0.f); v11 = fmaxf(v11, 0.f);
            }
            *(float2*)&C[(size_t)m0 * ldc + n0]       = make_float2(v00, v01);
            *(float2*)&C[(size_t)(m0 + 8) * ldc + n0] = make_float2(v10, v11);
        }
    }
#undef GLOAD
#undef SSTORE
}

// ---------------- per-head time coords ----------------
__global__ void __launch_bounds__(256) head_time_kernel(
    const float* __restrict__ q, const float* __restrict__ k,
    const float* __restrict__ v,
    float* __restrict__ qt, float* __restrict__ kt, float* __restrict__ vt)
{
    int w = (blockIdx.x * 256 + threadIdx.x) >> 5;
    int lane = threadIdx.x & 31;
    int tsr = w >> 16;
    int rem = w & 65535;
    int bh = rem >> 10;
    int s = rem & 1023;
    int b = bh >> 4, h = bh & 15;
    const float* src = (tsr == 0) ? q : (tsr == 1) ? k : v;
    float* dst = (tsr == 0) ? qt : (tsr == 1) ? kt : vt;
    const float* p = src + (size_t)(b * SEQ + s) * DIMV + h * DH;
    float v0 = p[lane], v1 = p[lane + 32];
    float sum = v0 * v0 + v1 * v1;
    sum = warpSum(sum);
    if (lane == 0) dst[rem] = sqrtf(sum + 1.0f);
}

// ---------------- fused flash attention (tf32 MMA, online softmax) ----------------
// Per block: (bh, 64 query rows). Q aug with qt col (k=72), K aug with -kt col,
// V aug with vt col (n=72). Output: lorentz-normalized space part to osp.
// Softmax denom cancels in the normalization, so it is never divided out.
__global__ void __launch_bounds__(128) flash_kernel(
    const float* __restrict__ qsp, const float* __restrict__ ksp,
    const float* __restrict__ vsp,
    const float* __restrict__ qt, const float* __restrict__ kt,
    const float* __restrict__ vt,
    float* __restrict__ osp)
{
    const int bh = blockIdx.y, b = bh >> 4, h = bh & 15;
    const int i0 = blockIdx.x * 64;
    const int t = threadIdx.x, lane = t & 31, warp = t >> 5;

    // KP: K B-frags [kf9][ng8][li32][slot2] = 4608 u32 (18KB), aliased by
    // P A-frags  [wm4][kf8][slot4][lane32] = 4096 u32 (16KB)
    __shared__ unsigned KP[4608];
    __shared__ unsigned Vb[4608];   // V B-frags [kf8][ng9][li32][slot2]

    // Q A-fragments (rows warp*16..+16, k=0..71): qa[kf][slot]
    unsigned qa[9][4];
    {
        const int r0 = lane >> 2;
        const int klo = lane & 3;
        #pragma unroll
        for (int kf = 0; kf < 9; kf++) {
            #pragma unroll
            for (int s = 0; s < 4; s++) {
                int r = warp * 16 + r0 + ((s & 1) ? 8 : 0);
                int kk = kf * 8 + klo + ((s >= 2) ? 4 : 0);
                float vq;
                if (kk < 64)
                    vq = qsp[(size_t)(b * SEQ + i0 + r) * DIMV + h * DH + kk];
                else if (kk == 64)
                    vq = qt[bh * SEQ + i0 + r];
                else
                    vq = 0.f;
                qa[kf][s] = f2tf32(vq);
            }
        }
    }

    float oacc[9][4];
    #pragma unroll
    for (int nf = 0; nf < 9; nf++)
        #pragma unroll
        for (int s = 0; s < 4; s++) oacc[nf][s] = 0.f;
    float m0 = -1e30f, m1 = -1e30f;

    for (int jt = 0; jt < 16; jt++) {
        __syncthreads();
        // cooperative load of K and V tiles into fragment-order smem
        const int j0 = jt * 64;
        for (int it = 0; it < 36; it++) {
            int idx = it * 128 + t;          // 0..4607
            int j = idx / 72, d = idx - j * 72;
            float kv, vv;
            if (d < 64) {
                size_t g = (size_t)(b * SEQ + j0 + j) * DIMV + h * DH + d;
                kv = ksp[g]; vv = vsp[g];
            } else if (d == 64) {
                kv = -kt[bh * SEQ + j0 + j];
                vv =  vt[bh * SEQ + j0 + j];
            } else { kv = 0.f; vv = 0.f; }
            // K as B: n=j, k=d
            int ksl = ((d & 7) >= 4) ? 1 : 0;
            KP[(((d >> 3) * 8 + (j >> 3)) * 32 + (j & 7) * 4 + (d & 3)) * 2 + ksl] = f2tf32(kv);
            // V as B: n=d, k=j
            int vsl = ((j & 7) >= 4) ? 1 : 0;
            Vb[(((j >> 3) * 9 + (d >> 3)) * 32 + (d & 7) * 4 + (j & 3)) * 2 + vsl] = f2tf32(vv);
        }
        __syncthreads();

        // S = Qa * Ka^T  (64x64 per block; warp does 16 rows)
        float sacc[8][4];
        #pragma unroll
        for (int nf = 0; nf < 8; nf++)
            #pragma unroll
            for (int s = 0; s < 4; s++) sacc[nf][s] = 0.f;
        #pragma unroll
        for (int kf = 0; kf < 9; kf++) {
            #pragma unroll
            for (int nf = 0; nf < 8; nf++) {
                uint2 bv = *(const uint2*)&KP[((kf * 8 + nf) * 32 + lane) * 2];
                mma_tf32(sacc[nf], qa[kf][0], qa[kf][1], qa[kf][2], qa[kf][3],
                         bv.x, bv.y);
            }
        }

        // logits = 0.25 * S ; online softmax for 2 rows per thread
        float mx0 = -1e30f, mx1 = -1e30f;
        #pragma unroll
        for (int nf = 0; nf < 8; nf++) {
            #pragma unroll
            for (int s = 0; s < 4; s++) sacc[nf][s] *= 0.25f;
            mx0 = fmaxf(mx0, fmaxf(sacc[nf][0], sacc[nf][1]));
            mx1 = fmaxf(mx1, fmaxf(sacc[nf][2], sacc[nf][3]));
        }
        mx0 = fmaxf(mx0, __shfl_xor_sync(0xffffffffu, mx0, 1));
        mx0 = fmaxf(mx0, __shfl_xor_sync(0xffffffffu, mx0, 2));
        mx1 = fmaxf(mx1, __shfl_xor_sync(0xffffffffu, mx1, 1));
        mx1 = fmaxf(mx1, __shfl_xor_sync(0xffffffffu, mx1, 2));
        float m0n = fmaxf(m0, mx0), m1n = fmaxf(m1, mx1);
        float corr0 = expf(m0 - m0n), corr1 = expf(m1 - m1n);
        m0 = m0n; m1 = m1n;
        #pragma unroll
        for (int nf = 0; nf < 8; nf++) {
            sacc[nf][0] = expf(sacc[nf][0] - m0n);
            sacc[nf][1] = expf(sacc[nf][1] - m0n);
            sacc[nf][2] = expf(sacc[nf][2] - m1n);
            sacc[nf][3] = expf(sacc[nf][3] - m1n);
        }

        __syncthreads();   // all warps done reading KP before P overwrite

        // scatter P into A-fragment order (warp-local region of KP)
        {
            const int r0 = lane >> 2;
            #pragma unroll
            for (int nf = 0; nf < 8; nf++) {
                #pragma unroll
                for (int s = 0; s < 4; s++) {
                    // s: 0 -> (r0, c0), 1 -> (r0, c1) ... C layout: [0]=(r0,c0) [1]=(r0,c1) [2]=(r1,c0) [3]=(r1,c1)
                    int r = r0 + ((s >= 2) ? 8 : 0);
                    int c = nf * 8 + (lane & 3) * 2 + (s & 1);
                    int cp = c & 7;
                    int slot = ((r >= 8) ? 1 : 0) | ((cp >= 4) ? 2 : 0);
                    int li = (r & 7) * 4 + (cp & 3);
                    KP[((warp * 8 + nf) * 4 + slot) * 32 + li] = f2tf32(sacc[nf][s]);
                }
            }
        }
        __syncwarp();

        // rescale O accumulators
        #pragma unroll
        for (int nf = 0; nf < 9; nf++) {
            oacc[nf][0] *= corr0; oacc[nf][1] *= corr0;
            oacc[nf][2] *= corr1; oacc[nf][3] *= corr1;
        }

        // O += P * Vaug  (k = 64 keys, n = 72)
        #pragma unroll
        for (int kf = 0; kf < 8; kf++) {
            unsigned pa[4];
            #pragma unroll
            for (int s = 0; s < 4; s++)
                pa[s] = KP[((warp * 8 + kf) * 4 + s) * 32 + lane];
            #pragma unroll
            for (int nf = 0; nf < 9; nf++) {
                uint2 bv = *(const uint2*)&Vb[((kf * 9 + nf) * 32 + lane) * 2];
                mma_tf32(oacc[nf], pa[0], pa[1], pa[2], pa[3], bv.x, bv.y);
            }
        }
    }

    // lorentz normalize rows (softmax denom cancels): out = O / sqrt(|sum(sp^2)-t^2|)
    float ss0 = 0.f, ss1 = 0.f;
    #pragma unroll
    for (int nf = 0; nf < 8; nf++) {
        ss0 += oacc[nf][0] * oacc[nf][0] + oacc[nf][1] * oacc[nf][1];
        ss1 += oacc[nf][2] * oacc[nf][2] + oacc[nf][3] * oacc[nf][3];
    }
    ss0 += __shfl_xor_sync(0xffffffffu, ss0, 1);
    ss0 += __shfl_xor_sync(0xffffffffu, ss0, 2);
    ss1 += __shfl_xor_sync(0xffffffffu, ss1, 1);
    ss1 += __shfl_xor_sync(0xffffffffu, ss1, 2);
    // time = col 64 -> nfrag 8, col offset 0, held by lanes with (lane&3)==0
    float t0 = __shfl_sync(0xffffffffu, oacc[8][0], lane & ~3);
    float t1 = __shfl_sync(0xffffffffu, oacc[8][2], lane & ~3);
    float rn0 = 1.0f / sqrtf(fmaxf(fabsf(ss0 - t0 * t0), 1e-8f));
    float rn1 = 1.0f / sqrtf(fmaxf(fabsf(ss1 - t1 * t1), 1e-8f));

    {
        int r0 = warp * 16 + (lane >> 2);
        int r1 = r0 + 8;
        #pragma unroll
        for (int nf = 0; nf < 8; nf++) {
            int c = nf * 8 + (lane & 3) * 2;
            *(float2*)&osp[(size_t)(b * SEQ + i0 + r0) * DIMV + h * DH + c] =
                make_float2(oacc[nf][0] * rn0, oacc[nf][1] * rn0);
            *(float2*)&osp[(size_t)(b * SEQ + i0 + r1) * DIMV + h * DH + c] =
                make_float2(oacc[nf][2] * rn1, oacc[nf][3] * rn1);
        }
    }
}

// ---------------- row time ----------------
__global__ void __launch_bounds__(256) row_time_kernel(
    const float* __restrict__ src, float* __restrict__ dst, int W)
{
    int m = blockIdx.x, t = threadIdx.x;
    __shared__ float red[32];
    float s = 0.f;
    for (int d = t; d < W; d += 256) {
        float vv = src[(size_t)m * W + d];
        s += vv * vv;
    }
    s = blockSum(s, red);
    if (t == 0) dst[m] = sqrtf(s + 1.0f);
}

// ---------------- fused: add_time -> midpoint -> hyp_layernorm -> add_time ----------------
__global__ void __launch_bounds__(256) mid_ln_kernel(
    const float* __restrict__ ysp, const float* __restrict__ xfull,
    const float* __restrict__ g, const float* __restrict__ bb,
    float* __restrict__ out)
{
    __shared__ float red[32];
    const int m = blockIdx.x, t = threadIdx.x;
    const float* y = ysp + (size_t)m * DIMV;
    const float* x = xfull + (size_t)m * DV;
    float a4[4];
    float sy = 0.f, sa = 0.f, sa2 = 0.f;
    #pragma unroll
    for (int i = 0; i < 4; i++) {
        int d = t + i * 256;
        float yy = y[d];
        float aa = 0.5f * (yy + x[1 + d]);
        a4[i] = aa;
        sy += yy * yy; sa += aa; sa2 += aa * aa;
    }
    float syT = blockSum(sy, red);
    float saT = blockSum(sa, red);
    float sa2T = blockSum(sa2, red);
    float zt = sqrtf(syT + 1.0f);
    float at = 0.5f * (zt + x[0]);
    float inner = sa2T - at * at;
    float rin = 1.0f / sqrtf(fmaxf(fabsf(inner), 1e-8f));
    float mu = saT * rin * (1.0f / 1024.0f);
    float sv = 0.f;
    #pragma unroll
    for (int i = 0; i < 4; i++) {
        float df = a4[i] * rin - mu;
        sv += df * df;
    }
    float var = blockSum(sv, red) * (1.0f / 1024.0f);
    float rstd = rsqrtf(var + 1e-5f);
    float ss = 0.f;
    float* o = out + (size_t)m * DV;
    #pragma unroll
    for (int i = 0; i < 4; i++) {
        int d = t + i * 256;
        float s = (a4[i] * rin - mu) * rstd * g[d] + bb[d];
        o[1 + d] = s;
        ss += s * s;
    }
    float ssT = blockSum(ss, red);
    if (t == 0) o[0] = sqrtf(ssT + 1.0f);
}

// ---------------- launch ----------------
extern "C" void kernel_launch(void* const* d_in, const int* in_sizes, int n_in,
                              void* d_out, int out_size)
{
    const float* x    = (const float*)d_in[0];
    const float* Wq   = (const float*)d_in[1];
    const float* bq   = (const float*)d_in[2];
    const float* Wk   = (const float*)d_in[3];
    const float* bk   = (const float*)d_in[4];
    const float* Wv   = (const float*)d_in[5];
    const float* bv   = (const float*)d_in[6];
    const float* Wo   = (const float*)d_in[7];
    const float* bo   = (const float*)d_in[8];
    const float* ln1g = (const float*)d_in[9];
    const float* ln1b = (const float*)d_in[10];
    const float* W1   = (const float*)d_in[11];
    const float* c1   = (const float*)d_in[12];
    const float* W2   = (const float*)d_in[13];
    const float* c2   = (const float*)d_in[14];
    const float* ln2g = (const float*)d_in[15];
    const float* ln2b = (const float*)d_in[16];
    float* out = (float*)d_out;

    float *q, *k, *v, *qt, *kt, *vt, *attn, *x2t, *y, *x1, *h, *ht, *y2;
    cudaGetSymbolAddress((void**)&q,   g_q);
    cudaGetSymbolAddress((void**)&k,   g_k);
    cudaGetSymbolAddress((void**)&v,   g_v);
    cudaGetSymbolAddress((void**)&qt,  g_qt);
    cudaGetSymbolAddress((void**)&kt,  g_kt);
    cudaGetSymbolAddress((void**)&vt,  g_vt);
    cudaGetSymbolAddress((void**)&attn, g_attn);
    cudaGetSymbolAddress((void**)&x2t, g_x2t);
    cudaGetSymbolAddress((void**)&y,   g_y);
    cudaGetSymbolAddress((void**)&x1,  g_x1);
    cudaGetSymbolAddress((void**)&h,   g_h);
    cudaGetSymbolAddress((void**)&ht,  g_ht);
    cudaGetSymbolAddress((void**)&y2,  g_y2);

    // fused QKV projections (tf32 tensor cores)
    mm_tf32<<<dim3(DIMV / 256, NTOK / 128, 3), 256>>>(
        x, DV, nullptr,
        Wq, Wk, Wv, DV, 0,
        bq, bk, bv,
        q, k, v, DIMV, DV, 0);

    head_time_kernel<<<24576, 256>>>(q, k, v, qt, kt, vt);

    // fused flash attention (replaces scores + softmax + ave)
    flash_kernel<<<dim3(16, NBH), 128>>>(q, k, v, qt, kt, vt, attn);

    row_time_kernel<<<NTOK, 256>>>(attn, x2t, DIMV);
    mm_tf32<<<dim3(DIMV / 256, NTOK / 128, 1), 256>>>(
        attn, DIMV, x2t,
        Wo, Wo, Wo, DV, 1,
        bo, bo, bo,
        y, y, y, DIMV, DIMV, 0);

    mid_ln_kernel<<<NTOK, 256>>>(y, x, ln1g, ln1b, x1);

    mm_tf32<<<dim3(MLPD / 256, NTOK / 128, 1), 256>>>(
        x1, DV, nullptr,
        W1, W1, W1, DV, 0,
        c1, c1, c1,
        h, h, h, MLPD, DV, 1);
    row_time_kernel<<<NTOK, 256>>>(h, ht, MLPD);
    mm_tf32<<<dim3(DIMV / 256, NTOK / 128, 1), 256>>>(
        h, MLPD, ht,
        W2, W2, W2, MLPD + 1, 1,
        c2, c2, c2,
        y2, y2, y2, DIMV, MLPD, 0);

    mid_ln_kernel<<<NTOK, 256>>>(y2, x1, ln2g, ln2b, out);
}

// round 17
// speedup vs baseline: 2.7584x; 1.0854x over previous
#include <cuda_runtime.h>
#include <math.h>

#define BATCH 4
#define SEQ   1024
#define NTOK  4096
#define DIMV  1024
#define DV    1025
#define HEADS 16
#define DH    64
#define NBH   64
#define MLPD  4096

// ---------------- scratch (device globals; allocation-free) ----------------
__device__ float g_q[NTOK * DIMV];
__device__ float g_k[NTOK * DIMV];
__device__ float g_v[NTOK * DIMV];
__device__ float g_qt[NBH * SEQ];
__device__ float g_kt[NBH * SEQ];
__device__ float g_vt[NBH * SEQ];
__device__ float g_attn[NTOK * DIMV];
__device__ float g_x2t[NTOK];
__device__ float g_y[NTOK * DIMV];
__device__ float g_x1[NTOK * DV];
__device__ float g_h[(size_t)NTOK * MLPD];
__device__ float g_ht[NTOK];
__device__ float g_y2[NTOK * DIMV];

// ---------------- reduction helpers ----------------
__device__ __forceinline__ float warpSum(float v) {
    #pragma unroll
    for (int o = 16; o; o >>= 1) v += __shfl_down_sync(0xffffffffu, v, o);
    return v;
}
__device__ __forceinline__ float blockSum(float v, float* red) {
    int lane = threadIdx.x & 31, w = threadIdx.x >> 5;
    v = warpSum(v);
    if (lane == 0) red[w] = v;
    __syncthreads();
    if (w == 0) {
        float r = (lane < (int)(blockDim.x >> 5)) ? red[lane] : 0.f;
        r = warpSum(r);
        if (lane == 0) red[0] = r;
    }
    __syncthreads();
    float out = red[0];
    __syncthreads();
    return out;
}

// ---------------- tf32 helpers ----------------
// raw fp32 bits as tf32 operand: HW uses top 19 bits (truncation rounding).
__device__ __forceinline__ unsigned f2t(float x) { return __float_as_uint(x); }

__device__ __forceinline__ void mma_tf32(float c[4],
    unsigned a0, unsigned a1, unsigned a2, unsigned a3,
    unsigned b0, unsigned b1)
{
    asm volatile(
        "mma.sync.aligned.m16n8k8.row.col.f32.tf32.tf32.f32 "
        "{%0,%1,%2,%3}, {%4,%5,%6,%7}, {%8,%9}, {%0,%1,%2,%3};"
        : "+f"(c[0]), "+f"(c[1]), "+f"(c[2]), "+f"(c[3])
        : "r"(a0), "r"(a1), "r"(a2), "r"(a3), "r"(b0), "r"(b1));
}

// ---------------- tf32 tensor-core GEMM (R9-validated structure) ----------------
// C[m,n] = sum_{k<Ks} A[m,k] * W[n, koff+k]
//        + (At ? At[m] * W[n*ldw + 0] : 0)  + bias[n];  optional ReLU.
// 128x256 tile, BK=16, 256 threads, 8 warps of 64x64, double-buffered
// fragment-order smem with scalar stores (validated). A loads vectorize
// to float4 when lda%4==0 and Ks%16==0 (O and W2 GEMMs).
__global__ void __launch_bounds__(256, 1) mm_tf32(
    const float* __restrict__ A, int lda,
    const float* __restrict__ At,
    const float* __restrict__ Wa, const float* __restrict__ Wb, const float* __restrict__ Wc,
    int ldw, int koff,
    const float* __restrict__ bia, const float* __restrict__ bib, const float* __restrict__ bic,
    float* __restrict__ Ca, float* __restrict__ Cb, float* __restrict__ Cc,
    int ldc, int Ks, int relu)
{
    const int z = blockIdx.z;
    const float* W    = (z == 0) ? Wa  : (z == 1) ? Wb  : Wc;
    const float* bias = (z == 0) ? bia : (z == 1) ? bib : bic;
    float*       C    = (z == 0) ? Ca  : (z == 1) ? Cb  : Cc;

    __shared__ unsigned As[2][2][2][4][4][32];
    __shared__ unsigned Bs[2][2][32][32][2];

    const int t = threadIdx.x;
    const int lane = t & 31, warp = t >> 5;
    const int wm = warp >> 2;
    const int wn = warp & 3;
    const int bm = blockIdx.y * 128;
    const int bn = blockIdx.x * 256;

    const int ar = t >> 2;
    const int ac = (t & 3) * 4;

    const bool vecA = ((lda & 3) == 0) && ((Ks & 15) == 0);

    float pfA[8];
    float pfB[16];

    float acc[4][8][4];
    #pragma unroll
    for (int mf = 0; mf < 4; mf++)
        #pragma unroll
        for (int nf = 0; nf < 8; nf++)
            #pragma unroll
            for (int s = 0; s < 4; s++) acc[mf][nf][s] = 0.f;

    const int ntile = (Ks + 15) >> 4;

#define GLOAD(K0)                                                            \
    {                                                                        \
        if (vecA) {                                                          \
            float4 va = *(const float4*)&A[(size_t)(bm + ar) * lda + (K0) + ac];      \
            float4 vb = *(const float4*)&A[(size_t)(bm + ar + 64) * lda + (K0) + ac]; \
            pfA[0] = va.x; pfA[1] = va.y; pfA[2] = va.z; pfA[3] = va.w;      \
            pfA[4] = vb.x; pfA[5] = vb.y; pfA[6] = vb.z; pfA[7] = vb.w;      \
        } else {                                                             \
            _Pragma("unroll")                                                \
            for (int j = 0; j < 4; j++) {                                    \
                int kg = (K0) + ac + j;                                      \
                bool p = kg < Ks;                                            \
                pfA[j]     = p ? A[(size_t)(bm + ar) * lda + kg] : 0.f;      \
                pfA[4 + j] = p ? A[(size_t)(bm + ar + 64) * lda + kg] : 0.f; \
            }                                                                \
        }                                                                    \
        _Pragma("unroll")                                                    \
        for (int pp = 0; pp < 4; pp++) {                                     \
            int n = bn + ar + pp * 64;                                       \
            _Pragma("unroll")                                                \
            for (int j = 0; j < 4; j++) {                                    \
                int kg = (K0) + ac + j;                                      \
                pfB[pp * 4 + j] = (kg < Ks)                                  \
                    ? W[(size_t)n * ldw + koff + kg] : 0.f;                  \
            }                                                                \
        }                                                                    \
    }

#define SSTORE(BUF)                                                          \
    {                                                                        \
        _Pragma("unroll")                                                    \
        for (int half = 0; half < 2; half++) {                               \
            int ml = ar + half * 64;                                         \
            int rr = ml & 15, mf = (ml >> 4) & 3, wmi = ml >> 6;             \
            _Pragma("unroll")                                                \
            for (int j = 0; j < 4; j++) {                                    \
                int kk = ac + j;                                             \
                int k8 = kk >> 3, cp = kk & 7;                               \
                int slot = ((rr >> 3) & 1) | ((cp >= 4) ? 2 : 0);            \
                int li = (rr & 7) * 4 + (cp & 3);                            \
                As[BUF][k8][wmi][mf][slot][li] = f2t(pfA[half * 4 + j]);     \
            }                                                                \
        }                                                                    \
        _Pragma("unroll")                                                    \
        for (int pp = 0; pp < 4; pp++) {                                     \
            int nl = ar + pp * 64;                                           \
            int ng = nl >> 3, n8 = nl & 7;                                   \
            _Pragma("unroll")                                                \
            for (int j = 0; j < 4; j++) {                                    \
                int kk = ac + j;                                             \
                int k8 = kk >> 3, cp = kk & 7;                               \
                int slot = (cp >= 4) ? 1 : 0;                                \
                int li = n8 * 4 + (cp & 3);                                  \
                Bs[BUF][k8][ng][li][slot] = f2t(pfB[pp * 4 + j]);            \
            }                                                                \
        }                                                                    \
    }

    GLOAD(0);
    SSTORE(0);
    __syncthreads();

    int buf = 0;
    for (int tile = 0; tile < ntile; tile++) {
        if (tile + 1 < ntile) GLOAD((tile + 1) << 4);

        #pragma unroll
        for (int k8 = 0; k8 < 2; k8++) {
            unsigned af[4][4];
            #pragma unroll
            for (int mf = 0; mf < 4; mf++)
                #pragma unroll
                for (int s = 0; s < 4; s++)
                    af[mf][s] = As[buf][k8][wm][mf][s][lane];
            unsigned bfr[8][2];
            #pragma unroll
            for (int nf = 0; nf < 8; nf++) {
                uint2 bv = *(const uint2*)&Bs[buf][k8][wn * 8 + nf][lane][0];
                bfr[nf][0] = bv.x; bfr[nf][1] = bv.y;
            }
            #pragma unroll
            for (int mf = 0; mf < 4; mf++)
                #pragma unroll
                for (int nf = 0; nf < 8; nf++)
                    mma_tf32(acc[mf][nf],
                             af[mf][0], af[mf][1], af[mf][2], af[mf][3],
                             bfr[nf][0], bfr[nf][1]);
        }

        if (tile + 1 < ntile) SSTORE(buf ^ 1);
        __syncthreads();
        buf ^= 1;
    }

    #pragma unroll
    for (int mf = 0; mf < 4; mf++) {
        int m0 = bm + wm * 64 + mf * 16 + (lane >> 2);
        float at0 = 0.f, at1 = 0.f;
        if (At) { at0 = At[m0]; at1 = At[m0 + 8]; }
        #pragma unroll
        for (int nf = 0; nf < 8; nf++) {
            int n0 = bn + wn * 64 + nf * 8 + (lane & 3) * 2;
            float wt0 = 0.f, wt1 = 0.f;
            if (At) { wt0 = W[(size_t)n0 * ldw]; wt1 = W[(size_t)(n0 + 1) * ldw]; }
            float b0v = bias[n0], b1v = bias[n0 + 1];
            float v00 = acc[mf][nf][0] + at0 * wt0 + b0v;
            float v01 = acc[mf][nf][1] + at0 * wt1 + b1v;
            float v10 = acc[mf][nf][2] + at1 * wt0 + b0v;
            float v11 = acc[mf][nf][3] + at1 * wt1 + b1v;
            if (relu) {
                v00 = fmaxf(v00, 0.f); v01 = fmaxf(v01, 0.f);
                v10 = fmaxf(v10, 0.f); v11 = fmaxf(v11, 0.f);
            }
            *(float2*)&C[(size_t)m0 * ldc + n0]       = make_float2(v00, v01);
            *(float2*)&C[(size_t)(m0 + 8) * ldc + n0] = make_float2(v10, v11);
        }
    }
#undef GLOAD
#undef SSTORE
}

// ---------------- per-head time coords ----------------
__global__ void __launch_bounds__(256) head_time_kernel(
    const float* __restrict__ q, const float* __restrict__ k,
    const float* __restrict__ v,
    float* __restrict__ qt, float* __restrict__ kt, float* __restrict__ vt)
{
    int w = (blockIdx.x * 256 + threadIdx.x) >> 5;
    int lane = threadIdx.x & 31;
    int tsr = w >> 16;
    int rem = w & 65535;
    int bh = rem >> 10;
    int s = rem & 1023;
    int b = bh >> 4, h = bh & 15;
    const float* src = (tsr == 0) ? q : (tsr == 1) ? k : v;
    float* dst = (tsr == 0) ? qt : (tsr == 1) ? kt : vt;
    const float* p = src + (size_t)(b * SEQ + s) * DIMV + h * DH;
    float v0 = p[lane], v1 = p[lane + 32];
    float sum = v0 * v0 + v1 * v1;
    sum = warpSum(sum);
    if (lane == 0) dst[rem] = sqrtf(sum + 1.0f);
}

// ---------------- fused flash attention (tf32 MMA, online softmax) ----------------
__global__ void __launch_bounds__(128) flash_kernel(
    const float* __restrict__ qsp, const float* __restrict__ ksp,
    const float* __restrict__ vsp,
    const float* __restrict__ qt, const float* __restrict__ kt,
    const float* __restrict__ vt,
    float* __restrict__ osp)
{
    const int bh = blockIdx.y, b = bh >> 4, h = bh & 15;
    const int i0 = blockIdx.x * 64;
    const int t = threadIdx.x, lane = t & 31, warp = t >> 5;

    __shared__ unsigned KP[4608];   // K B-frags, aliased by P A-frags
    __shared__ unsigned Vb[4608];   // V B-frags

    unsigned qa[9][4];
    {
        const int r0 = lane >> 2;
        const int klo = lane & 3;
        #pragma unroll
        for (int kf = 0; kf < 9; kf++) {
            #pragma unroll
            for (int s = 0; s < 4; s++) {
                int r = warp * 16 + r0 + ((s & 1) ? 8 : 0);
                int kk = kf * 8 + klo + ((s >= 2) ? 4 : 0);
                float vq;
                if (kk < 64)
                    vq = qsp[(size_t)(b * SEQ + i0 + r) * DIMV + h * DH + kk];
                else if (kk == 64)
                    vq = qt[bh * SEQ + i0 + r];
                else
                    vq = 0.f;
                qa[kf][s] = f2t(vq);
            }
        }
    }

    float oacc[9][4];
    #pragma unroll
    for (int nf = 0; nf < 9; nf++)
        #pragma unroll
        for (int s = 0; s < 4; s++) oacc[nf][s] = 0.f;
    float m0 = -1e30f, m1 = -1e30f;

    for (int jt = 0; jt < 16; jt++) {
        __syncthreads();
        const int j0 = jt * 64;
        for (int it = 0; it < 36; it++) {
            int idx = it * 128 + t;
            int j = idx / 72, d = idx - j * 72;
            float kv, vv;
            if (d < 64) {
                size_t g = (size_t)(b * SEQ + j0 + j) * DIMV + h * DH + d;
                kv = ksp[g]; vv = vsp[g];
            } else if (d == 64) {
                kv = -kt[bh * SEQ + j0 + j];
                vv =  vt[bh * SEQ + j0 + j];
            } else { kv = 0.f; vv = 0.f; }
            int ksl = ((d & 7) >= 4) ? 1 : 0;
            KP[(((d >> 3) * 8 + (j >> 3)) * 32 + (j & 7) * 4 + (d & 3)) * 2 + ksl] = f2t(kv);
            int vsl = ((j & 7) >= 4) ? 1 : 0;
            Vb[(((j >> 3) * 9 + (d >> 3)) * 32 + (d & 7) * 4 + (j & 3)) * 2 + vsl] = f2t(vv);
        }
        __syncthreads();

        float sacc[8][4];
        #pragma unroll
        for (int nf = 0; nf < 8; nf++)
            #pragma unroll
            for (int s = 0; s < 4; s++) sacc[nf][s] = 0.f;
        #pragma unroll
        for (int kf = 0; kf < 9; kf++) {
            #pragma unroll
            for (int nf = 0; nf < 8; nf++) {
                uint2 bv = *(const uint2*)&KP[((kf * 8 + nf) * 32 + lane) * 2];
                mma_tf32(sacc[nf], qa[kf][0], qa[kf][1], qa[kf][2], qa[kf][3],
                         bv.x, bv.y);
            }
        }

        float mx0 = -1e30f, mx1 = -1e30f;
        #pragma unroll
        for (int nf = 0; nf < 8; nf++) {
            #pragma unroll
            for (int s = 0; s < 4; s++) sacc[nf][s] *= 0.25f;
            mx0 = fmaxf(mx0, fmaxf(sacc[nf][0], sacc[nf][1]));
            mx1 = fmaxf(mx1, fmaxf(sacc[nf][2], sacc[nf][3]));
        }
        mx0 = fmaxf(mx0, __shfl_xor_sync(0xffffffffu, mx0, 1));
        mx0 = fmaxf(mx0, __shfl_xor_sync(0xffffffffu, mx0, 2));
        mx1 = fmaxf(mx1, __shfl_xor_sync(0xffffffffu, mx1, 1));
        mx1 = fmaxf(mx1, __shfl_xor_sync(0xffffffffu, mx1, 2));
        float m0n = fmaxf(m0, mx0), m1n = fmaxf(m1, mx1);
        float corr0 = __expf(m0 - m0n), corr1 = __expf(m1 - m1n);
        m0 = m0n; m1 = m1n;
        #pragma unroll
        for (int nf = 0; nf < 8; nf++) {
            sacc[nf][0] = __expf(sacc[nf][0] - m0n);
            sacc[nf][1] = __expf(sacc[nf][1] - m0n);
            sacc[nf][2] = __expf(sacc[nf][2] - m1n);
            sacc[nf][3] = __expf(sacc[nf][3] - m1n);
        }

        __syncthreads();

        {
            const int r0 = lane >> 2;
            #pragma unroll
            for (int nf = 0; nf < 8; nf++) {
                #pragma unroll
                for (int s = 0; s < 4; s++) {
                    int r = r0 + ((s >= 2) ? 8 : 0);
                    int c = nf * 8 + (lane & 3) * 2 + (s & 1);
                    int cp = c & 7;
                    int slot = ((r >= 8) ? 1 : 0) | ((cp >= 4) ? 2 : 0);
                    int li = (r & 7) * 4 + (cp & 3);
                    KP[((warp * 8 + nf) * 4 + slot) * 32 + li] = f2t(sacc[nf][s]);
                }
            }
        }
        __syncwarp();

        #pragma unroll
        for (int nf = 0; nf < 9; nf++) {
            oacc[nf][0] *= corr0; oacc[nf][1] *= corr0;
            oacc[nf][2] *= corr1; oacc[nf][3] *= corr1;
        }

        #pragma unroll
        for (int kf = 0; kf < 8; kf++) {
            unsigned pa[4];
            #pragma unroll
            for (int s = 0; s < 4; s++)
                pa[s] = KP[((warp * 8 + kf) * 4 + s) * 32 + lane];
            #pragma unroll
            for (int nf = 0; nf < 9; nf++) {
                uint2 bv = *(const uint2*)&Vb[((kf * 9 + nf) * 32 + lane) * 2];
                mma_tf32(oacc[nf], pa[0], pa[1], pa[2], pa[3], bv.x, bv.y);
            }
        }
    }

    float ss0 = 0.f, ss1 = 0.f;
    #pragma unroll
    for (int nf = 0; nf < 8; nf++) {
        ss0 += oacc[nf][0] * oacc[nf][0] + oacc[nf][1] * oacc[nf][1];
        ss1 += oacc[nf][2] * oacc[nf][2] + oacc[nf][3] * oacc[nf][3];
    }
    ss0 += __shfl_xor_sync(0xffffffffu, ss0, 1);
    ss0 += __shfl_xor_sync(0xffffffffu, ss0, 2);
    ss1 += __shfl_xor_sync(0xffffffffu, ss1, 1);
    ss1 += __shfl_xor_sync(0xffffffffu, ss1, 2);
    float t0 = __shfl_sync(0xffffffffu, oacc[8][0], lane & ~3);
    float t1 = __shfl_sync(0xffffffffu, oacc[8][2], lane & ~3);
    float rn0 = 1.0f / sqrtf(fmaxf(fabsf(ss0 - t0 * t0), 1e-8f));
    float rn1 = 1.0f / sqrtf(fmaxf(fabsf(ss1 - t1 * t1), 1e-8f));

    {
        int r0 = warp * 16 + (lane >> 2);
        int r1 = r0 + 8;
        #pragma unroll
        for (int nf = 0; nf < 8; nf++) {
            int c = nf * 8 + (lane & 3) * 2;
            *(float2*)&osp[(size_t)(b * SEQ + i0 + r0) * DIMV + h * DH + c] =
                make_float2(oacc[nf][0] * rn0, oacc[nf][1] * rn0);
            *(float2*)&osp[(size_t)(b * SEQ + i0 + r1) * DIMV + h * DH + c] =
                make_float2(oacc[nf][2] * rn1, oacc[nf][3] * rn1);
        }
    }
}

// ---------------- row time ----------------
__global__ void __launch_bounds__(256) row_time_kernel(
    const float* __restrict__ src, float* __restrict__ dst, int W)
{
    int m = blockIdx.x, t = threadIdx.x;
    __shared__ float red[32];
    float s = 0.f;
    for (int d = t; d < W; d += 256) {
        float vv = src[(size_t)m * W + d];
        s += vv * vv;
    }
    s = blockSum(s, red);
    if (t == 0) dst[m] = sqrtf(s + 1.0f);
}

// ---------------- fused: add_time -> midpoint -> hyp_layernorm -> add_time ----------------
__global__ void __launch_bounds__(256) mid_ln_kernel(
    const float* __restrict__ ysp, const float* __restrict__ xfull,
    const float* __restrict__ g, const float* __restrict__ bb,
    float* __restrict__ out)
{
    __shared__ float red[32];
    const int m = blockIdx.x, t = threadIdx.x;
    const float* y = ysp + (size_t)m * DIMV;
    const float* x = xfull + (size_t)m * DV;
    float a4[4];
    float sy = 0.f, sa = 0.f, sa2 = 0.f;
    #pragma unroll
    for (int i = 0; i < 4; i++) {
        int d = t + i * 256;
        float yy = y[d];
        float aa = 0.5f * (yy + x[1 + d]);
        a4[i] = aa;
        sy += yy * yy; sa += aa; sa2 += aa * aa;
    }
    float syT = blockSum(sy, red);
    float saT = blockSum(sa, red);
    float sa2T = blockSum(sa2, red);
    float zt = sqrtf(syT + 1.0f);
    float at = 0.5f * (zt + x[0]);
    float inner = sa2T - at * at;
    float rin = 1.0f / sqrtf(fmaxf(fabsf(inner), 1e-8f));
    float mu = saT * rin * (1.0f / 1024.0f);
    float sv = 0.f;
    #pragma unroll
    for (int i = 0; i < 4; i++) {
        float df = a4[i] * rin - mu;
        sv += df * df;
    }
    float var = blockSum(sv, red) * (1.0f / 1024.0f);
    float rstd = rsqrtf(var + 1e-5f);
    float ss = 0.f;
    float* o = out + (size_t)m * DV;
    #pragma unroll
    for (int i = 0; i < 4; i++) {
        int d = t + i * 256;
        float s = (a4[i] * rin - mu) * rstd * g[d] + bb[d];
        o[1 + d] = s;
        ss += s * s;
    }
    float ssT = blockSum(ss, red);
    if (t == 0) o[0] = sqrtf(ssT + 1.0f);
}

// ---------------- launch ----------------
extern "C" void kernel_launch(void* const* d_in, const int* in_sizes, int n_in,
                              void* d_out, int out_size)
{
    const float* x    = (const float*)d_in[0];
    const float* Wq   = (const float*)d_in[1];
    const float* bq   = (const float*)d_in[2];
    const float* Wk   = (const float*)d_in[3];
    const float* bk   = (const float*)d_in[4];
    const float* Wv   = (const float*)d_in[5];
    const float* bv   = (const float*)d_in[6];
    const float* Wo   = (const float*)d_in[7];
    const float* bo   = (const float*)d_in[8];
    const float* ln1g = (const float*)d_in[9];
    const float* ln1b = (const float*)d_in[10];
    const float* W1   = (const float*)d_in[11];
    const float* c1   = (const float*)d_in[12];
    const float* W2   = (const float*)d_in[13];
    const float* c2   = (const float*)d_in[14];
    const float* ln2g = (const float*)d_in[15];
    const float* ln2b = (const float*)d_in[16];
    float* out = (float*)d_out;

    float *q, *k, *v, *qt, *kt, *vt, *attn, *x2t, *y, *x1, *h, *ht, *y2;
    cudaGetSymbolAddress((void**)&q,   g_q);
    cudaGetSymbolAddress((void**)&k,   g_k);
    cudaGetSymbolAddress((void**)&v,   g_v);
    cudaGetSymbolAddress((void**)&qt,  g_qt);
    cudaGetSymbolAddress((void**)&kt,  g_kt);
    cudaGetSymbolAddress((void**)&vt,  g_vt);
    cudaGetSymbolAddress((void**)&attn, g_attn);
    cudaGetSymbolAddress((void**)&x2t, g_x2t);
    cudaGetSymbolAddress((void**)&y,   g_y);
    cudaGetSymbolAddress((void**)&x1,  g_x1);
    cudaGetSymbolAddress((void**)&h,   g_h);
    cudaGetSymbolAddress((void**)&ht,  g_ht);
    cudaGetSymbolAddress((void**)&y2,  g_y2);

    // fused QKV projections (tf32 tensor cores)
    mm_tf32<<<dim3(DIMV / 256, NTOK / 128, 3), 256>>>(
        x, DV, nullptr,
        Wq, Wk, Wv, DV, 0,
        bq, bk, bv,
        q, k, v, DIMV, DV, 0);

    head_time_kernel<<<24576, 256>>>(q, k, v, qt, kt, vt);

    flash_kernel<<<dim3(16, NBH), 128>>>(q, k, v, qt, kt, vt, attn);

    row_time_kernel<<<NTOK, 256>>>(attn, x2t, DIMV);
    mm_tf32<<<dim3(DIMV / 256, NTOK / 128, 1), 256>>>(
        attn, DIMV, x2t,
        Wo, Wo, Wo, DV, 1,
        bo, bo, bo,
        y, y, y, DIMV, DIMV, 0);

    mid_ln_kernel<<<NTOK, 256>>>(y, x, ln1g, ln1b, x1);

    mm_tf32<<<dim3(MLPD / 256, NTOK / 128, 1), 256>>>(
        x1, DV, nullptr,
        W1, W1, W1, DV, 0,
        c1, c1, c1,
        h, h, h, MLPD, DV, 1);
    row_time_kernel<<<NTOK, 256>>>(h, ht, MLPD);
    mm_tf32<<<dim3(DIMV / 256, NTOK / 128, 1), 256>>>(
        h, MLPD, ht,
        W2, W2, W2, MLPD + 1, 1,
        c2, c2, c2,
        y2, y2, y2, DIMV, MLPD, 0);

    mid_ln_kernel<<<NTOK, 256>>>(y2, x1, ln2g, ln2b, out);
}